// round 13
// baseline (speedup 1.0000x reference)
#include <cuda_runtime.h>
#include <cuda_fp16.h>
#include <math.h>
#include <cstdint>

// Problem constants
#define T_ 4096
#define B_ 4
#define E_ 512
#define CK_ 1024
#define H_ 8
#define HD_ 64
#define NB_ (B_ * E_)   // 2048

typedef __half f16;

// ---------------- scratch (__device__ globals) ------------------------------
__device__ f16 g_xnth[(size_t)T_ * NB_];        // X      [16384][512]
__device__ f16 g_xth [(size_t)NB_ * T_];        // X^T    [2048][4096]
__device__ f16 g_wqh[E_*E_], g_wkh[E_*E_], g_wvh[E_*E_], g_woh[E_*E_];
__device__ f16 g_wch[(size_t)2*CK_*T_];         // [Wck;Wcv] stacked
__device__ f16 g_qh [(size_t)T_*B_*E_];
__device__ f16 g_kvinh[(size_t)2*CK_*NB_];      // [kin;vin] stacked
__device__ f16 g_kh [(size_t)CK_*B_*E_];
__device__ f16 g_vh [(size_t)CK_*B_*E_];
__device__ f16 g_atth[(size_t)T_*B_*E_];

// ---------------- helpers ---------------------------------------------------
__device__ __forceinline__ uint32_t smem_u32(const void* p) {
    uint32_t a;
    asm("{ .reg .u64 t; cvta.to.shared.u64 t, %1; cvt.u32.u64 %0, t; }" : "=r"(a) : "l"(p));
    return a;
}
__device__ __forceinline__ uint32_t swz(uint32_t off) { return off ^ ((off >> 3) & 0x70); }

#define LDSM_X4(r0, r1, r2, r3, addr) \
    asm volatile("ldmatrix.sync.aligned.m8n8.x4.shared.b16 {%0,%1,%2,%3}, [%4];" \
        : "=r"(r0), "=r"(r1), "=r"(r2), "=r"(r3) : "r"(addr))
#define LDSM_X2_T(r0, r1, addr) \
    asm volatile("ldmatrix.sync.aligned.m8n8.x2.trans.shared.b16 {%0,%1}, [%2];" \
        : "=r"(r0), "=r"(r1) : "r"(addr))
#define CP_ASYNC16(dst, src) \
    asm volatile("cp.async.cg.shared.global [%0], [%1], 16;" :: "r"(dst), "l"(src))
#define CP_COMMIT() asm volatile("cp.async.commit_group;" ::: "memory")
#define CP_WAIT2()  asm volatile("cp.async.wait_group 2;" ::: "memory")
#define CP_WAIT1()  asm volatile("cp.async.wait_group 1;" ::: "memory")
#define CP_WAIT0()  asm volatile("cp.async.wait_group 0;" ::: "memory")

__device__ __forceinline__ void mma16816(float* c, const uint32_t* a, const uint32_t* b) {
    asm volatile("mma.sync.aligned.m16n8k16.row.col.f32.f16.f16.f32 "
                 "{%0,%1,%2,%3}, {%4,%5,%6,%7}, {%8,%9}, {%0,%1,%2,%3};"
                 : "+f"(c[0]), "+f"(c[1]), "+f"(c[2]), "+f"(c[3])
                 : "r"(a[0]), "r"(a[1]), "r"(a[2]), "r"(a[3]), "r"(b[0]), "r"(b[1]));
}

__device__ __forceinline__ uint32_t pack2_h16(float x0, float x1) {
    f16 h0 = __float2half_rn(x0), h1 = __float2half_rn(x1);
    return (uint32_t)__half_as_ushort(h0) | ((uint32_t)__half_as_ushort(h1) << 16);
}

// ---------------------------------------------------------------------------
// Batched elementwise convert fp32 -> fp16 (grid.y selects job, up to 4)
// ---------------------------------------------------------------------------
struct SplitJobs {
    const float4* src[4];
    uint2* h[4];
    int n4[4];
};

__global__ void split_many(SplitJobs j)
{
    const int y = blockIdx.y;
    const float4* __restrict__ src = j.src[y];
    uint2* __restrict__ h = j.h[y];
    const int n4 = j.n4[y];
    for (int i = blockIdx.x * blockDim.x + threadIdx.x; i < n4;
         i += gridDim.x * blockDim.x) {
        float4 x = src[i];
        h[i] = make_uint2(pack2_h16(x.x, x.y), pack2_h16(x.z, x.w));
    }
}

// Fused query convert: X[T][2048] fp32 -> fp16 normal AND transposed
__global__ __launch_bounds__(256) void splitq_kernel(
    const float* __restrict__ X,
    f16* __restrict__ Xnh, f16* __restrict__ Xth)
{
    __shared__ float tile[32][36];
    int n0 = blockIdx.x * 32, t0 = blockIdx.y * 32;
    {
        int row = threadIdx.x >> 3, q = threadIdx.x & 7;
        float4 v = *(const float4*)(X + (size_t)(t0 + row) * NB_ + n0 + q * 4);
        size_t on = ((size_t)(t0 + row) * NB_ + n0 + q * 4) * 2;
        *(uint2*)((char*)Xnh + on) =
            make_uint2(pack2_h16(v.x, v.y), pack2_h16(v.z, v.w));
        tile[row][q * 4 + 0] = v.x; tile[row][q * 4 + 1] = v.y;
        tile[row][q * 4 + 2] = v.z; tile[row][q * 4 + 3] = v.w;
    }
    __syncthreads();
    {
        int n = threadIdx.x >> 3, tg = threadIdx.x & 7;
        float v0 = tile[tg * 4 + 0][n], v1 = tile[tg * 4 + 1][n];
        float v2 = tile[tg * 4 + 2][n], v3 = tile[tg * 4 + 3][n];
        size_t o = ((size_t)(n0 + n) * T_ + t0 + tg * 4) * 2;
        *(uint2*)((char*)Xth + o) =
            make_uint2(pack2_h16(v0, v1), pack2_h16(v2, v3));
    }
}

// ---------------------------------------------------------------------------
// HMMA GEMM: C = A·B^T, single fp16, warp tile 32x64, 8 warps, 2 CTA/SM.
// Tile 128x128, K-chunk 64, 3-stage cp.async pipeline (96KB).
// grid.z selects arg set. MODE 0: fp32 out | MODE 1: fp16 out
// ---------------------------------------------------------------------------
struct GemmArgs {
    const f16 *Ah, *Bh;
    const float* bias;
    float* Cf;
    f16* Ch;
};

template<int MODE>
__global__ __launch_bounds__(256, 2) void hmma_ps(
    GemmArgs a0, GemmArgs a1, int M, int N, int K, float scale)
{
    extern __shared__ char sm[];
    constexpr uint32_t STG = 32768;
    constexpr uint32_t OAH = 0, OBH = 16384;
    const GemmArgs a = blockIdx.z ? a1 : a0;
    const int tid = threadIdx.x, wid = tid >> 5, lane = tid & 31;
    const int warp_m = wid & 3, warp_n = wid >> 2;
    const int m0 = blockIdx.y * 128, n0 = blockIdx.x * 128;
    const uint32_t sb = smem_u32(sm);

    const int a_row = warp_m * 32 + (lane & 15);
    const int a_k   = (lane >> 4) * 8;
    const int b_n   = warp_n * 64 + (lane & 7) + (lane >> 4) * 8;
    const int b_k   = ((lane >> 3) & 1) * 8;

    float acc[2][8][4];
#pragma unroll
    for (int i = 0; i < 2; i++)
#pragma unroll
        for (int j = 0; j < 8; j++)
#pragma unroll
            for (int r = 0; r < 4; r++) acc[i][j][r] = 0.f;

    auto stage = [&](int buf, int k0) {
        uint32_t base = sb + (uint32_t)buf * STG;
#pragma unroll
        for (int l = 0; l < 4; l++) {
            int idx = l * 256 + tid;
            int row = idx >> 3, c16 = (idx & 7) << 4;
            uint32_t off = swz((uint32_t)row * 128u + (uint32_t)c16);
            size_t ga = ((size_t)(m0 + row) * K + k0) * 2 + c16;
            size_t gb = ((size_t)(n0 + row) * K + k0) * 2 + c16;
            CP_ASYNC16(base + OAH + off, (const char*)a.Ah + ga);
            CP_ASYNC16(base + OBH + off, (const char*)a.Bh + gb);
        }
    };

    const int nc = K >> 6;
    stage(0, 0);  CP_COMMIT();
    stage(1, 64); CP_COMMIT();

    for (int kt = 0; kt < nc; kt++) {
        if (kt + 1 < nc) { CP_WAIT1(); } else { CP_WAIT0(); }
        __syncthreads();
        if (kt + 2 < nc) { stage((kt + 2) % 3, (kt + 2) * 64); CP_COMMIT(); }

        const uint32_t base = sb + (uint32_t)(kt % 3) * STG;
#pragma unroll
        for (int ks = 0; ks < 4; ks++) {
            uint32_t afh[2][4], bfh[4][4];
#pragma unroll
            for (int mt = 0; mt < 2; mt++) {
                uint32_t off = swz((uint32_t)(a_row + mt * 16) * 128u
                                   + (uint32_t)(ks * 16 + a_k) * 2u);
                LDSM_X4(afh[mt][0], afh[mt][1], afh[mt][2], afh[mt][3], base + OAH + off);
            }
#pragma unroll
            for (int nt = 0; nt < 4; nt++) {
                uint32_t off = swz((uint32_t)(b_n + nt * 16) * 128u
                                   + (uint32_t)(ks * 16 + b_k) * 2u);
                LDSM_X4(bfh[nt][0], bfh[nt][1], bfh[nt][2], bfh[nt][3], base + OBH + off);
            }
#pragma unroll
            for (int mt = 0; mt < 2; mt++)
#pragma unroll
                for (int n8 = 0; n8 < 8; n8++)
                    mma16816(acc[mt][n8], afh[mt], &bfh[n8 >> 1][(n8 & 1) * 2]);
        }
    }

    // ---- epilogue
    const int g = lane >> 2, t = lane & 3;
#pragma unroll
    for (int mt = 0; mt < 2; mt++) {
        int r0 = m0 + warp_m * 32 + mt * 16 + g;
#pragma unroll
        for (int n8 = 0; n8 < 8; n8++) {
            int col = n0 + warp_n * 64 + n8 * 8 + t * 2;
            float b0 = a.bias ? a.bias[col] : 0.f, b1 = a.bias ? a.bias[col + 1] : 0.f;
            float v0 = (acc[mt][n8][0] + b0) * scale, v1 = (acc[mt][n8][1] + b1) * scale;
            float v2 = (acc[mt][n8][2] + b0) * scale, v3 = (acc[mt][n8][3] + b1) * scale;
            if (MODE == 0) {
                *(float2*)(a.Cf + (size_t)r0 * N + col) = make_float2(v0, v1);
                *(float2*)(a.Cf + (size_t)(r0 + 8) * N + col) = make_float2(v2, v3);
            } else {
                *(uint32_t*)((char*)a.Ch + ((size_t)r0 * N + col) * 2) = pack2_h16(v0, v1);
                *(uint32_t*)((char*)a.Ch + ((size_t)(r0 + 8) * N + col) * 2) = pack2_h16(v2, v3);
            }
        }
    }
}

// ---------------------------------------------------------------------------
// HMMA flash attention, single fp16, Q fragments hoisted, 4-buffer KV ring
// (prefetch depth 3). grid (T_half/128, B*H); Q/O pointers pre-offset for the
// T-half. smem: Q 16KB + 4 x 16KB KV = 80KB -> 2 CTA/SM.
// ---------------------------------------------------------------------------
__global__ __launch_bounds__(256, 2) void flash_hmma(
    const f16* __restrict__ Qh, const f16* __restrict__ Kh,
    const f16* __restrict__ Vh, f16* __restrict__ Oh)
{
    extern __shared__ char sm[];
    constexpr uint32_t SQH = 0, SKV = 16384, KSTG = 16384;
    constexpr uint32_t OK = 0, OVH = 8192;
    constexpr int NT = CK_ / 64;   // 16
    const int tid = threadIdx.x, wid = tid >> 5, lane = tid & 31;
    const int bh = blockIdx.y, b = bh >> 3, h = bh & 7;
    const int t0 = blockIdx.x * 128;
    const uint32_t sb = smem_u32(sm);

#pragma unroll
    for (int l = 0; l < 4; l++) {
        int idx = l * 256 + tid;
        int row = idx >> 3, cc = (idx & 7) << 4;
        uint32_t off = swz((uint32_t)row * 128u + (uint32_t)cc);
        size_t gq = (((size_t)(t0 + row) * B_ + b) * E_ + h * 64) * 2 + cc;
        *(uint4*)(sm + SQH + off) = *(const uint4*)((const char*)Qh + gq);
    }

    auto stage_kv = [&](int buf, int kt) {
        uint32_t base = sb + SKV + (uint32_t)buf * KSTG;
#pragma unroll
        for (int l = 0; l < 2; l++) {
            int idx = l * 256 + tid;
            int row = idx >> 3, cc = (idx & 7) << 4;
            uint32_t off = swz((uint32_t)row * 128u + (uint32_t)cc);
            size_t gk = (((size_t)(kt * 64 + row) * B_ + b) * E_ + h * 64) * 2 + cc;
            CP_ASYNC16(base + OK  + off, (const char*)Kh + gk);
            CP_ASYNC16(base + OVH + off, (const char*)Vh + gk);
        }
    };

    const int a_row = 16 * wid + (lane & 15);
    const int a_k   = (lane >> 4) * 8;
    const int b_n   = (lane & 7) + (lane >> 4) * 8;
    const int b_k   = ((lane >> 3) & 1) * 8;
    const int g = lane >> 2, t = lane & 3;

    stage_kv(0, 0); CP_COMMIT();
    stage_kv(1, 1); CP_COMMIT();
    stage_kv(2, 2); CP_COMMIT();

    // ---- hoist Q fragments (barrier also covers Q smem stores)
    __syncthreads();
    uint32_t qf[4][4];
#pragma unroll
    for (int ks = 0; ks < 4; ks++) {
        uint32_t ad = sb + SQH + swz((uint32_t)a_row * 128u
                                     + (uint32_t)(ks * 16 + a_k) * 2u);
        LDSM_X4(qf[ks][0], qf[ks][1], qf[ks][2], qf[ks][3], ad);
    }

    float m_run[2] = {-1e30f, -1e30f}, l_run[2] = {0.f, 0.f};
    float o_acc[8][4];
#pragma unroll
    for (int j = 0; j < 8; j++)
#pragma unroll
        for (int r = 0; r < 4; r++) o_acc[j][r] = 0.f;

    for (int kt = 0; kt < NT; kt++) {
        int rem = NT - 1 - kt;
        if (rem >= 2)      { CP_WAIT2(); }
        else if (rem == 1) { CP_WAIT1(); }
        else               { CP_WAIT0(); }
        __syncthreads();                        // tile kt visible; prior tile fully read
        if (kt + 3 < NT) { stage_kv((kt + 3) & 3, kt + 3); CP_COMMIT(); }

        const uint32_t kvb = sb + SKV + (uint32_t)(kt & 3) * KSTG;

        // ---- S = Q·K^T
        float s[8][4];
#pragma unroll
        for (int j = 0; j < 8; j++)
#pragma unroll
            for (int r = 0; r < 4; r++) s[j][r] = 0.f;

#pragma unroll
        for (int ks = 0; ks < 4; ks++) {
            uint32_t bfr[4][4];
#pragma unroll
            for (int nt = 0; nt < 4; nt++) {
                uint32_t bd = kvb + OK + swz((uint32_t)(b_n + nt * 16) * 128u
                                             + (uint32_t)(ks * 16 + b_k) * 2u);
                LDSM_X4(bfr[nt][0], bfr[nt][1], bfr[nt][2], bfr[nt][3], bd);
            }
#pragma unroll
            for (int n8 = 0; n8 < 8; n8++)
                mma16816(s[n8], qf[ks], &bfr[n8 >> 1][(n8 & 1) * 2]);
        }

        // ---- online softmax
        float mn[2];
#pragma unroll
        for (int r = 0; r < 2; r++) {
            float v = -1e30f;
#pragma unroll
            for (int j = 0; j < 8; j++)
                v = fmaxf(v, fmaxf(s[j][r * 2], s[j][r * 2 + 1]));
            v = fmaxf(v, __shfl_xor_sync(0xffffffffu, v, 1));
            v = fmaxf(v, __shfl_xor_sync(0xffffffffu, v, 2));
            mn[r] = fmaxf(v, m_run[r]);
        }
        uint32_t ph2[8][2];
        float rs[2] = {0.f, 0.f};
#pragma unroll
        for (int j = 0; j < 8; j++) {
#pragma unroll
            for (int r = 0; r < 2; r++) {
                float p0 = __expf(s[j][r * 2]     - mn[r]);
                float p1 = __expf(s[j][r * 2 + 1] - mn[r]);
                rs[r] += p0 + p1;
                ph2[j][r] = pack2_h16(p0, p1);
            }
        }
#pragma unroll
        for (int r = 0; r < 2; r++) {
            float v = rs[r];
            v += __shfl_xor_sync(0xffffffffu, v, 1);
            v += __shfl_xor_sync(0xffffffffu, v, 2);
            float f = __expf(m_run[r] - mn[r]);
            l_run[r] = l_run[r] * f + v;
            m_run[r] = mn[r];
#pragma unroll
            for (int j = 0; j < 8; j++) {
                o_acc[j][r * 2]     *= f;
                o_acc[j][r * 2 + 1] *= f;
            }
        }

        // ---- O += P·V
#pragma unroll
        for (int ks = 0; ks < 4; ks++) {
            uint32_t af[4] = {ph2[2 * ks][0], ph2[2 * ks][1],
                              ph2[2 * ks + 1][0], ph2[2 * ks + 1][1]};
#pragma unroll
            for (int n8 = 0; n8 < 8; n8++) {
                uint32_t vrow = swz((uint32_t)(ks * 16 + (lane & 15)) * 128u
                                    + (uint32_t)(n8 * 16));
                uint32_t h0, h1;
                LDSM_X2_T(h0, h1, kvb + OVH + vrow);
                uint32_t bvh[2] = {h0, h1};
                mma16816(o_acc[n8], af, bvh);
            }
        }
        __syncthreads();   // all warps done with buffer kt before re-stage
    }

    float inv[2] = {1.f / l_run[0], 1.f / l_run[1]};
#pragma unroll
    for (int n8 = 0; n8 < 8; n8++) {
        int col = h * 64 + n8 * 8 + t * 2;
#pragma unroll
        for (int r = 0; r < 2; r++) {
            int row = t0 + 16 * wid + g + r * 8;
            float v0 = o_acc[n8][r * 2] * inv[r];
            float v1 = o_acc[n8][r * 2 + 1] * inv[r];
            size_t off = (((size_t)row * B_ + b) * E_ + col) * 2;
            *(uint32_t*)((char*)Oh + off) = pack2_h16(v0, v1);
        }
    }
}

// ---------------------------------------------------------------------------
extern "C" void kernel_launch(void* const* d_in, const int* in_sizes, int n_in,
                              void* d_out, int out_size)
{
    const float* query = (const float*)d_in[0];
    const float* Wq    = (const float*)d_in[1];
    const float* bq    = (const float*)d_in[2];
    const float* Wk    = (const float*)d_in[3];
    const float* bk    = (const float*)d_in[4];
    const float* Wv    = (const float*)d_in[5];
    const float* bv    = (const float*)d_in[6];
    const float* Wck   = (const float*)d_in[7];
    const float* Wcv   = (const float*)d_in[8];
    const float* Wo    = (const float*)d_in[9];
    const float* bo    = (const float*)d_in[10];
    float* out = (float*)d_out;

    f16 *xnth, *xth, *wqh, *wkh, *wvh, *woh, *wch, *qh, *kvinh, *kh, *vh, *atth;
    cudaGetSymbolAddress((void**)&xnth, g_xnth);
    cudaGetSymbolAddress((void**)&xth,  g_xth);
    cudaGetSymbolAddress((void**)&wqh,  g_wqh);
    cudaGetSymbolAddress((void**)&wkh,  g_wkh);
    cudaGetSymbolAddress((void**)&wvh,  g_wvh);
    cudaGetSymbolAddress((void**)&woh,  g_woh);
    cudaGetSymbolAddress((void**)&wch,  g_wch);
    cudaGetSymbolAddress((void**)&qh,   g_qh);
    cudaGetSymbolAddress((void**)&kvinh, g_kvinh);
    cudaGetSymbolAddress((void**)&kh,   g_kh);
    cudaGetSymbolAddress((void**)&vh,   g_vh);
    cudaGetSymbolAddress((void**)&atth, g_atth);

    f16 *kinh = kvinh;
    f16 *vinh = kvinh + (size_t)CK_ * NB_;

    static cudaStream_t s1 = nullptr;
    static cudaEvent_t eF = nullptr, eX = nullptr, eW = nullptr, e1 = nullptr;
    static cudaEvent_t eF1 = nullptr, eO1 = nullptr;
    if (!s1) {
        cudaStreamCreateWithFlags(&s1, cudaStreamNonBlocking);
        cudaEventCreateWithFlags(&eF, cudaEventDisableTiming);
        cudaEventCreateWithFlags(&eX, cudaEventDisableTiming);
        cudaEventCreateWithFlags(&eW, cudaEventDisableTiming);
        cudaEventCreateWithFlags(&e1, cudaEventDisableTiming);
        cudaEventCreateWithFlags(&eF1, cudaEventDisableTiming);
        cudaEventCreateWithFlags(&eO1, cudaEventDisableTiming);
    }

    const int GSM = 98304;   // 3 stages x 32KB -> 2 CTA/SM
    const int FSM = 81920;   // Q 16KB + 4 x 16KB KV ring
    cudaFuncSetAttribute(hmma_ps<0>, cudaFuncAttributeMaxDynamicSharedMemorySize, GSM);
    cudaFuncSetAttribute(hmma_ps<1>, cudaFuncAttributeMaxDynamicSharedMemorySize, GSM);
    cudaFuncSetAttribute(flash_hmma, cudaFuncAttributeMaxDynamicSharedMemorySize, FSM);

    // ---- fork: s1 joins capture via event recorded on origin stream
    cudaEventRecord(eF, 0);
    cudaStreamWaitEvent(s1, eF, 0);

    // ---- s0: X conversion, then compression weights
    splitq_kernel<<<dim3(NB_/32, T_/32), 256>>>(query, xnth, xth);
    cudaEventRecord(eX, 0);
    {
        SplitJobs jc;
        jc.src[0] = (const float4*)Wck; jc.h[0] = (uint2*)wch;                    jc.n4[0] = CK_*T_/4;
        jc.src[1] = (const float4*)Wcv; jc.h[1] = (uint2*)(wch + (size_t)CK_*T_); jc.n4[1] = CK_*T_/4;
        jc.src[2] = jc.src[0]; jc.h[2] = jc.h[0]; jc.n4[2] = 0;
        jc.src[3] = jc.src[0]; jc.h[3] = jc.h[0]; jc.n4[3] = 0;
        split_many<<<dim3(512, 2), 256>>>(jc);
    }

    // ---- s1 (concurrent): projection weights, then qproj after X ready
    {
        SplitJobs jw;
        jw.src[0] = (const float4*)Wq; jw.h[0] = (uint2*)wqh; jw.n4[0] = E_*E_/4;
        jw.src[1] = (const float4*)Wk; jw.h[1] = (uint2*)wkh; jw.n4[1] = E_*E_/4;
        jw.src[2] = (const float4*)Wv; jw.h[2] = (uint2*)wvh; jw.n4[2] = E_*E_/4;
        jw.src[3] = (const float4*)Wo; jw.h[3] = (uint2*)woh; jw.n4[3] = E_*E_/4;
        split_many<<<dim3(64, 4), 256, 0, s1>>>(jw);
        cudaEventRecord(eW, s1);
    }
    cudaStreamWaitEvent(s1, eX, 0);
    {
        GemmArgs qa = {xnth, wqh, bq, nullptr, qh};
        hmma_ps<1><<<dim3(4, 128, 1), 256, GSM, s1>>>(qa, qa, T_*B_, E_, E_, 0.125f);
        cudaEventRecord(e1, s1);
    }

    // ---- s0: merged compression [kin;vin] = [Wck;Wcv]·X^T  [2048x2048x4096]
    {
        GemmArgs ca = {wch, xth, nullptr, nullptr, kvinh};
        hmma_ps<1><<<dim3(16, 16, 1), 256, GSM>>>(ca, ca, 2*CK_, NB_, T_, 1.f);
    }

    // ---- s0: batched k/v projections (needs wk/wv from s1's split)
    cudaStreamWaitEvent(0, eW, 0);
    {
        GemmArgs ka = {kinh, wkh, bk, nullptr, kh};
        GemmArgs va = {vinh, wvh, bv, nullptr, vh};
        hmma_ps<1><<<dim3(4, 32, 2), 256, GSM>>>(ka, va, CK_*B_, E_, E_, 1.f);
    }

    // join q before flash
    cudaStreamWaitEvent(0, e1, 0);

    // ---- s0: flash half 1 (t in [0, 2048))
    flash_hmma<<<dim3(T_/256, B_*H_), 256, FSM>>>(qh, kh, vh, atth);
    cudaEventRecord(eF1, 0);

    // ---- s0: flash half 2 (t in [2048, 4096)) — Q/O pointers offset
    {
        const size_t toff = (size_t)(T_/2) * NB_;   // 2048 * 2048 elements
        flash_hmma<<<dim3(T_/256, B_*H_), 256, FSM>>>(qh + toff, kh, vh, atth + toff);
    }

    // ---- s1: out-projection half 1 (att rows [0, 8192)) concurrent w/ flash2
    cudaStreamWaitEvent(s1, eF1, 0);
    {
        GemmArgs oa = {atth, woh, bo, out, nullptr};
        hmma_ps<0><<<dim3(4, 64, 1), 256, GSM, s1>>>(oa, oa, T_*B_/2, E_, E_, 1.f);
        cudaEventRecord(eO1, s1);
    }

    // ---- s0: out-projection half 2 (att rows [8192, 16384))
    {
        const size_t roff = (size_t)(T_*B_/2) * E_;
        GemmArgs oa = {atth + roff, woh, bo, out + roff, nullptr};
        hmma_ps<0><<<dim3(4, 64, 1), 256, GSM>>>(oa, oa, T_*B_/2, E_, E_, 1.f);
    }

    // ---- join s1 back into origin stream (graph completeness)
    cudaStreamWaitEvent(0, eO1, 0);

    (void)in_sizes; (void)n_in; (void)out_size;
}

// round 14
// speedup vs baseline: 1.0613x; 1.0613x over previous
#include <cuda_runtime.h>
#include <cuda_fp16.h>
#include <math.h>
#include <cstdint>

// Problem constants
#define T_ 4096
#define B_ 4
#define E_ 512
#define CK_ 1024
#define H_ 8
#define HD_ 64
#define NB_ (B_ * E_)   // 2048

typedef __half f16;

// ---------------- scratch (__device__ globals) ------------------------------
__device__ f16 g_xnth[(size_t)T_ * NB_];        // X      [16384][512]
__device__ f16 g_xth [(size_t)NB_ * T_];        // X^T    [2048][4096]
__device__ f16 g_wqh[E_*E_], g_wkh[E_*E_], g_wvh[E_*E_], g_woh[E_*E_];
__device__ f16 g_wch[(size_t)2*CK_*T_];         // [Wck;Wcv] stacked
__device__ f16 g_qh [(size_t)T_*B_*E_];
__device__ f16 g_kvinh[(size_t)2*CK_*NB_];      // [kin;vin] stacked
__device__ f16 g_kh [(size_t)CK_*B_*E_];
__device__ f16 g_vh [(size_t)CK_*B_*E_];
__device__ f16 g_atth[(size_t)T_*B_*E_];

// ---------------- helpers ---------------------------------------------------
__device__ __forceinline__ uint32_t smem_u32(const void* p) {
    uint32_t a;
    asm("{ .reg .u64 t; cvta.to.shared.u64 t, %1; cvt.u32.u64 %0, t; }" : "=r"(a) : "l"(p));
    return a;
}
__device__ __forceinline__ uint32_t swz(uint32_t off) { return off ^ ((off >> 3) & 0x70); }

#define LDSM_X4(r0, r1, r2, r3, addr) \
    asm volatile("ldmatrix.sync.aligned.m8n8.x4.shared.b16 {%0,%1,%2,%3}, [%4];" \
        : "=r"(r0), "=r"(r1), "=r"(r2), "=r"(r3) : "r"(addr))
#define LDSM_X2_T(r0, r1, addr) \
    asm volatile("ldmatrix.sync.aligned.m8n8.x2.trans.shared.b16 {%0,%1}, [%2];" \
        : "=r"(r0), "=r"(r1) : "r"(addr))
#define CP_ASYNC16(dst, src) \
    asm volatile("cp.async.cg.shared.global [%0], [%1], 16;" :: "r"(dst), "l"(src))
#define CP_COMMIT() asm volatile("cp.async.commit_group;" ::: "memory")
#define CP_WAIT1()  asm volatile("cp.async.wait_group 1;" ::: "memory")
#define CP_WAIT0()  asm volatile("cp.async.wait_group 0;" ::: "memory")

__device__ __forceinline__ void mma16816(float* c, const uint32_t* a, const uint32_t* b) {
    asm volatile("mma.sync.aligned.m16n8k16.row.col.f32.f16.f16.f32 "
                 "{%0,%1,%2,%3}, {%4,%5,%6,%7}, {%8,%9}, {%0,%1,%2,%3};"
                 : "+f"(c[0]), "+f"(c[1]), "+f"(c[2]), "+f"(c[3])
                 : "r"(a[0]), "r"(a[1]), "r"(a[2]), "r"(a[3]), "r"(b[0]), "r"(b[1]));
}

__device__ __forceinline__ uint32_t pack2_h16(float x0, float x1) {
    f16 h0 = __float2half_rn(x0), h1 = __float2half_rn(x1);
    return (uint32_t)__half_as_ushort(h0) | ((uint32_t)__half_as_ushort(h1) << 16);
}

// ---------------------------------------------------------------------------
// Batched elementwise convert fp32 -> fp16 (grid.y selects job, 6 jobs)
// ---------------------------------------------------------------------------
struct SplitJobs {
    const float4* src[6];
    uint2* h[6];
    int n4[6];
};

__global__ void split_many(SplitJobs j)
{
    const int y = blockIdx.y;
    const float4* __restrict__ src = j.src[y];
    uint2* __restrict__ h = j.h[y];
    const int n4 = j.n4[y];
    for (int i = blockIdx.x * blockDim.x + threadIdx.x; i < n4;
         i += gridDim.x * blockDim.x) {
        float4 x = src[i];
        h[i] = make_uint2(pack2_h16(x.x, x.y), pack2_h16(x.z, x.w));
    }
}

// Fused query convert: X[T][2048] fp32 -> fp16 normal AND transposed
__global__ __launch_bounds__(256) void splitq_kernel(
    const float* __restrict__ X,
    f16* __restrict__ Xnh, f16* __restrict__ Xth)
{
    __shared__ float tile[32][36];
    int n0 = blockIdx.x * 32, t0 = blockIdx.y * 32;
    {
        int row = threadIdx.x >> 3, q = threadIdx.x & 7;
        float4 v = *(const float4*)(X + (size_t)(t0 + row) * NB_ + n0 + q * 4);
        size_t on = ((size_t)(t0 + row) * NB_ + n0 + q * 4) * 2;
        *(uint2*)((char*)Xnh + on) =
            make_uint2(pack2_h16(v.x, v.y), pack2_h16(v.z, v.w));
        tile[row][q * 4 + 0] = v.x; tile[row][q * 4 + 1] = v.y;
        tile[row][q * 4 + 2] = v.z; tile[row][q * 4 + 3] = v.w;
    }
    __syncthreads();
    {
        int n = threadIdx.x >> 3, tg = threadIdx.x & 7;
        float v0 = tile[tg * 4 + 0][n], v1 = tile[tg * 4 + 1][n];
        float v2 = tile[tg * 4 + 2][n], v3 = tile[tg * 4 + 3][n];
        size_t o = ((size_t)(n0 + n) * T_ + t0 + tg * 4) * 2;
        *(uint2*)((char*)Xth + o) =
            make_uint2(pack2_h16(v0, v1), pack2_h16(v2, v3));
    }
}

// ---------------------------------------------------------------------------
// GEMM tile core: C_tile = A[m0:m0+128]·B[n0:n0+128]^T (+bias)*scale.
// Single fp16 operands, warp tile 32x64, 8 warps, K-chunk 64,
// 3-stage cp.async pipeline. mode 0: fp32 out | mode 1: fp16 out.
// ---------------------------------------------------------------------------
struct GemmArgs {
    const f16 *Ah, *Bh;
    const float* bias;
    float* Cf;
    f16* Ch;
};

__device__ __forceinline__ void gemm_tile(
    const GemmArgs& a, int m0, int n0, int N, int K, float scale, int mode,
    char* sm)
{
    constexpr uint32_t STG = 32768;
    constexpr uint32_t OAH = 0, OBH = 16384;
    const int tid = threadIdx.x, wid = tid >> 5, lane = tid & 31;
    const int warp_m = wid & 3, warp_n = wid >> 2;
    const uint32_t sb = smem_u32(sm);

    const int a_row = warp_m * 32 + (lane & 15);
    const int a_k   = (lane >> 4) * 8;
    const int b_n   = warp_n * 64 + (lane & 7) + (lane >> 4) * 8;
    const int b_k   = ((lane >> 3) & 1) * 8;

    float acc[2][8][4];
#pragma unroll
    for (int i = 0; i < 2; i++)
#pragma unroll
        for (int j = 0; j < 8; j++)
#pragma unroll
            for (int r = 0; r < 4; r++) acc[i][j][r] = 0.f;

    auto stage = [&](int buf, int k0) {
        uint32_t base = sb + (uint32_t)buf * STG;
#pragma unroll
        for (int l = 0; l < 4; l++) {
            int idx = l * 256 + tid;
            int row = idx >> 3, c16 = (idx & 7) << 4;
            uint32_t off = swz((uint32_t)row * 128u + (uint32_t)c16);
            size_t ga = ((size_t)(m0 + row) * K + k0) * 2 + c16;
            size_t gb = ((size_t)(n0 + row) * K + k0) * 2 + c16;
            CP_ASYNC16(base + OAH + off, (const char*)a.Ah + ga);
            CP_ASYNC16(base + OBH + off, (const char*)a.Bh + gb);
        }
    };

    const int nc = K >> 6;
    stage(0, 0);  CP_COMMIT();
    stage(1, 64); CP_COMMIT();

    for (int kt = 0; kt < nc; kt++) {
        if (kt + 1 < nc) { CP_WAIT1(); } else { CP_WAIT0(); }
        __syncthreads();
        if (kt + 2 < nc) { stage((kt + 2) % 3, (kt + 2) * 64); CP_COMMIT(); }

        const uint32_t base = sb + (uint32_t)(kt % 3) * STG;
#pragma unroll
        for (int ks = 0; ks < 4; ks++) {
            uint32_t afh[2][4], bfh[4][4];
#pragma unroll
            for (int mt = 0; mt < 2; mt++) {
                uint32_t off = swz((uint32_t)(a_row + mt * 16) * 128u
                                   + (uint32_t)(ks * 16 + a_k) * 2u);
                LDSM_X4(afh[mt][0], afh[mt][1], afh[mt][2], afh[mt][3], base + OAH + off);
            }
#pragma unroll
            for (int nt = 0; nt < 4; nt++) {
                uint32_t off = swz((uint32_t)(b_n + nt * 16) * 128u
                                   + (uint32_t)(ks * 16 + b_k) * 2u);
                LDSM_X4(bfh[nt][0], bfh[nt][1], bfh[nt][2], bfh[nt][3], base + OBH + off);
            }
#pragma unroll
            for (int mt = 0; mt < 2; mt++)
#pragma unroll
                for (int n8 = 0; n8 < 8; n8++)
                    mma16816(acc[mt][n8], afh[mt], &bfh[n8 >> 1][(n8 & 1) * 2]);
        }
    }

    // ---- epilogue
    const int g = lane >> 2, t = lane & 3;
#pragma unroll
    for (int mt = 0; mt < 2; mt++) {
        int r0 = m0 + warp_m * 32 + mt * 16 + g;
#pragma unroll
        for (int n8 = 0; n8 < 8; n8++) {
            int col = n0 + warp_n * 64 + n8 * 8 + t * 2;
            float b0 = a.bias ? a.bias[col] : 0.f, b1 = a.bias ? a.bias[col + 1] : 0.f;
            float v0 = (acc[mt][n8][0] + b0) * scale, v1 = (acc[mt][n8][1] + b1) * scale;
            float v2 = (acc[mt][n8][2] + b0) * scale, v3 = (acc[mt][n8][3] + b1) * scale;
            if (mode == 0) {
                *(float2*)(a.Cf + (size_t)r0 * N + col) = make_float2(v0, v1);
                *(float2*)(a.Cf + (size_t)(r0 + 8) * N + col) = make_float2(v2, v3);
            } else {
                *(uint32_t*)((char*)a.Ch + ((size_t)r0 * N + col) * 2) = pack2_h16(v0, v1);
                *(uint32_t*)((char*)a.Ch + ((size_t)(r0 + 8) * N + col) * 2) = pack2_h16(v2, v3);
            }
        }
    }
}

// standard GEMM launch: 2-D grid of tiles, grid.z selects arg set
__global__ __launch_bounds__(256, 2) void hmma_ps(
    GemmArgs a0, GemmArgs a1, int N, int K, float scale, int mode)
{
    extern __shared__ char sm[];
    const GemmArgs a = blockIdx.z ? a1 : a0;
    gemm_tile(a, blockIdx.y * 128, blockIdx.x * 128, N, K, scale, mode, sm);
}

// fused compression + qproj: 1-D flattened grid; tiles [0,ntc) = job c
// (gxc tiles per row), rest = job q (gxq tiles per row)
__global__ __launch_bounds__(256, 2) void hmma_combo(
    GemmArgs c, int Nc, int Kc, int gxc, int ntc,
    GemmArgs q, int Nq, int Kq, int gxq, float qscale)
{
    extern __shared__ char sm[];
    int ti = blockIdx.x;
    if (ti < ntc) {
        gemm_tile(c, (ti / gxc) * 128, (ti % gxc) * 128, Nc, Kc, 1.f, 1, sm);
    } else {
        ti -= ntc;
        gemm_tile(q, (ti / gxq) * 128, (ti % gxq) * 128, Nq, Kq, qscale, 1, sm);
    }
}

// ---------------------------------------------------------------------------
// HMMA flash attention (R12 version): single fp16, Q fragments hoisted,
// 2-deep KV double buffer. grid (T/128, B*H); 256 threads.
// smem: Q 16KB + 2 x 16KB KV = 48KB -> 2 CTA/SM.
// ---------------------------------------------------------------------------
__global__ __launch_bounds__(256, 2) void flash_hmma(
    const f16* __restrict__ Qh, const f16* __restrict__ Kh,
    const f16* __restrict__ Vh, f16* __restrict__ Oh)
{
    extern __shared__ char sm[];
    constexpr uint32_t SQH = 0, SKV = 16384, KSTG = 16384;
    constexpr uint32_t OK = 0, OVH = 8192;
    const int tid = threadIdx.x, wid = tid >> 5, lane = tid & 31;
    const int bh = blockIdx.y, b = bh >> 3, h = bh & 7;
    const int t0 = blockIdx.x * 128;
    const uint32_t sb = smem_u32(sm);

#pragma unroll
    for (int l = 0; l < 4; l++) {
        int idx = l * 256 + tid;
        int row = idx >> 3, cc = (idx & 7) << 4;
        uint32_t off = swz((uint32_t)row * 128u + (uint32_t)cc);
        size_t gq = (((size_t)(t0 + row) * B_ + b) * E_ + h * 64) * 2 + cc;
        *(uint4*)(sm + SQH + off) = *(const uint4*)((const char*)Qh + gq);
    }

    auto stage_kv = [&](int buf, int kt) {
        uint32_t base = sb + SKV + (uint32_t)buf * KSTG;
#pragma unroll
        for (int l = 0; l < 2; l++) {
            int idx = l * 256 + tid;
            int row = idx >> 3, cc = (idx & 7) << 4;
            uint32_t off = swz((uint32_t)row * 128u + (uint32_t)cc);
            size_t gk = (((size_t)(kt * 64 + row) * B_ + b) * E_ + h * 64) * 2 + cc;
            CP_ASYNC16(base + OK  + off, (const char*)Kh + gk);
            CP_ASYNC16(base + OVH + off, (const char*)Vh + gk);
        }
    };

    const int a_row = 16 * wid + (lane & 15);
    const int a_k   = (lane >> 4) * 8;
    const int b_n   = (lane & 7) + (lane >> 4) * 8;
    const int b_k   = ((lane >> 3) & 1) * 8;
    const int g = lane >> 2, t = lane & 3;

    stage_kv(0, 0);
    CP_COMMIT();

    // ---- hoist Q fragments (barrier also covers Q smem stores)
    __syncthreads();
    uint32_t qf[4][4];
#pragma unroll
    for (int ks = 0; ks < 4; ks++) {
        uint32_t ad = sb + SQH + swz((uint32_t)a_row * 128u
                                     + (uint32_t)(ks * 16 + a_k) * 2u);
        LDSM_X4(qf[ks][0], qf[ks][1], qf[ks][2], qf[ks][3], ad);
    }

    float m_run[2] = {-1e30f, -1e30f}, l_run[2] = {0.f, 0.f};
    float o_acc[8][4];
#pragma unroll
    for (int j = 0; j < 8; j++)
#pragma unroll
        for (int r = 0; r < 4; r++) o_acc[j][r] = 0.f;

    for (int kt = 0; kt < CK_ / 64; kt++) {
        if (kt + 1 < CK_ / 64) { stage_kv((kt + 1) & 1, kt + 1); CP_COMMIT(); CP_WAIT1(); }
        else                   { CP_WAIT0(); }
        __syncthreads();
        const uint32_t kvb = sb + SKV + (uint32_t)(kt & 1) * KSTG;

        // ---- S = Q·K^T
        float s[8][4];
#pragma unroll
        for (int j = 0; j < 8; j++)
#pragma unroll
            for (int r = 0; r < 4; r++) s[j][r] = 0.f;

#pragma unroll
        for (int ks = 0; ks < 4; ks++) {
            uint32_t bfr[4][4];
#pragma unroll
            for (int nt = 0; nt < 4; nt++) {
                uint32_t bd = kvb + OK + swz((uint32_t)(b_n + nt * 16) * 128u
                                             + (uint32_t)(ks * 16 + b_k) * 2u);
                LDSM_X4(bfr[nt][0], bfr[nt][1], bfr[nt][2], bfr[nt][3], bd);
            }
#pragma unroll
            for (int n8 = 0; n8 < 8; n8++)
                mma16816(s[n8], qf[ks], &bfr[n8 >> 1][(n8 & 1) * 2]);
        }

        // ---- online softmax
        float mn[2];
#pragma unroll
        for (int r = 0; r < 2; r++) {
            float v = -1e30f;
#pragma unroll
            for (int j = 0; j < 8; j++)
                v = fmaxf(v, fmaxf(s[j][r * 2], s[j][r * 2 + 1]));
            v = fmaxf(v, __shfl_xor_sync(0xffffffffu, v, 1));
            v = fmaxf(v, __shfl_xor_sync(0xffffffffu, v, 2));
            mn[r] = fmaxf(v, m_run[r]);
        }
        uint32_t ph2[8][2];
        float rs[2] = {0.f, 0.f};
#pragma unroll
        for (int j = 0; j < 8; j++) {
#pragma unroll
            for (int r = 0; r < 2; r++) {
                float p0 = __expf(s[j][r * 2]     - mn[r]);
                float p1 = __expf(s[j][r * 2 + 1] - mn[r]);
                rs[r] += p0 + p1;
                ph2[j][r] = pack2_h16(p0, p1);
            }
        }
#pragma unroll
        for (int r = 0; r < 2; r++) {
            float v = rs[r];
            v += __shfl_xor_sync(0xffffffffu, v, 1);
            v += __shfl_xor_sync(0xffffffffu, v, 2);
            float f = __expf(m_run[r] - mn[r]);
            l_run[r] = l_run[r] * f + v;
            m_run[r] = mn[r];
#pragma unroll
            for (int j = 0; j < 8; j++) {
                o_acc[j][r * 2]     *= f;
                o_acc[j][r * 2 + 1] *= f;
            }
        }

        // ---- O += P·V
#pragma unroll
        for (int ks = 0; ks < 4; ks++) {
            uint32_t af[4] = {ph2[2 * ks][0], ph2[2 * ks][1],
                              ph2[2 * ks + 1][0], ph2[2 * ks + 1][1]};
#pragma unroll
            for (int n8 = 0; n8 < 8; n8++) {
                uint32_t vrow = swz((uint32_t)(ks * 16 + (lane & 15)) * 128u
                                    + (uint32_t)(n8 * 16));
                uint32_t h0, h1;
                LDSM_X2_T(h0, h1, kvb + OVH + vrow);
                uint32_t bvh[2] = {h0, h1};
                mma16816(o_acc[n8], af, bvh);
            }
        }
        __syncthreads();
    }

    float inv[2] = {1.f / l_run[0], 1.f / l_run[1]};
#pragma unroll
    for (int n8 = 0; n8 < 8; n8++) {
        int col = h * 64 + n8 * 8 + t * 2;
#pragma unroll
        for (int r = 0; r < 2; r++) {
            int row = t0 + 16 * wid + g + r * 8;
            float v0 = o_acc[n8][r * 2] * inv[r];
            float v1 = o_acc[n8][r * 2 + 1] * inv[r];
            size_t off = (((size_t)row * B_ + b) * E_ + col) * 2;
            *(uint32_t*)((char*)Oh + off) = pack2_h16(v0, v1);
        }
    }
}

// ---------------------------------------------------------------------------
extern "C" void kernel_launch(void* const* d_in, const int* in_sizes, int n_in,
                              void* d_out, int out_size)
{
    const float* query = (const float*)d_in[0];
    const float* Wq    = (const float*)d_in[1];
    const float* bq    = (const float*)d_in[2];
    const float* Wk    = (const float*)d_in[3];
    const float* bk    = (const float*)d_in[4];
    const float* Wv    = (const float*)d_in[5];
    const float* bv    = (const float*)d_in[6];
    const float* Wck   = (const float*)d_in[7];
    const float* Wcv   = (const float*)d_in[8];
    const float* Wo    = (const float*)d_in[9];
    const float* bo    = (const float*)d_in[10];
    float* out = (float*)d_out;

    f16 *xnth, *xth, *wqh, *wkh, *wvh, *woh, *wch, *qh, *kvinh, *kh, *vh, *atth;
    cudaGetSymbolAddress((void**)&xnth, g_xnth);
    cudaGetSymbolAddress((void**)&xth,  g_xth);
    cudaGetSymbolAddress((void**)&wqh,  g_wqh);
    cudaGetSymbolAddress((void**)&wkh,  g_wkh);
    cudaGetSymbolAddress((void**)&wvh,  g_wvh);
    cudaGetSymbolAddress((void**)&woh,  g_woh);
    cudaGetSymbolAddress((void**)&wch,  g_wch);
    cudaGetSymbolAddress((void**)&qh,   g_qh);
    cudaGetSymbolAddress((void**)&kvinh, g_kvinh);
    cudaGetSymbolAddress((void**)&kh,   g_kh);
    cudaGetSymbolAddress((void**)&vh,   g_vh);
    cudaGetSymbolAddress((void**)&atth, g_atth);

    f16 *kinh = kvinh;
    f16 *vinh = kvinh + (size_t)CK_ * NB_;

    const int GSM = 98304;   // 3 stages x 32KB -> 2 CTA/SM
    const int FSM = 49152;   // Q 16KB + 2 x 16KB KV
    cudaFuncSetAttribute(hmma_ps,    cudaFuncAttributeMaxDynamicSharedMemorySize, GSM);
    cudaFuncSetAttribute(hmma_combo, cudaFuncAttributeMaxDynamicSharedMemorySize, GSM);
    cudaFuncSetAttribute(flash_hmma, cudaFuncAttributeMaxDynamicSharedMemorySize, FSM);

    // ---- 1) all weight converts in one launch
    {
        SplitJobs jw;
        jw.src[0] = (const float4*)Wq;  jw.h[0] = (uint2*)wqh; jw.n4[0] = E_*E_/4;
        jw.src[1] = (const float4*)Wk;  jw.h[1] = (uint2*)wkh; jw.n4[1] = E_*E_/4;
        jw.src[2] = (const float4*)Wv;  jw.h[2] = (uint2*)wvh; jw.n4[2] = E_*E_/4;
        jw.src[3] = (const float4*)Wo;  jw.h[3] = (uint2*)woh; jw.n4[3] = E_*E_/4;
        jw.src[4] = (const float4*)Wck; jw.h[4] = (uint2*)wch; jw.n4[4] = CK_*T_/4;
        jw.src[5] = (const float4*)Wcv;
        jw.h[5] = (uint2*)(wch + (size_t)CK_*T_);
        jw.n4[5] = CK_*T_/4;
        split_many<<<dim3(256, 6), 256>>>(jw);
    }

    // ---- 2) X convert (normal + transposed)
    splitq_kernel<<<dim3(NB_/32, T_/32), 256>>>(query, xnth, xth);

    // ---- 3) fused compression + qproj (one 768-CTA launch)
    {
        GemmArgs ca = {wch, xth, nullptr, nullptr, kvinh};   // [kin;vin] = [Wck;Wcv]·X^T
        GemmArgs qa = {xnth, wqh, bq, nullptr, qh};          // q = (X·Wq^T+bq)*0.125
        hmma_combo<<<256 + 512, 256, GSM>>>(
            ca, NB_, T_, /*gxc=*/16, /*ntc=*/256,
            qa, E_, E_, /*gxq=*/4, 0.125f);
    }

    // ---- 4) batched k/v projections
    {
        GemmArgs ka = {kinh, wkh, bk, nullptr, kh};
        GemmArgs va = {vinh, wvh, bv, nullptr, vh};
        hmma_ps<<<dim3(4, 32, 2), 256, GSM>>>(ka, va, E_, E_, 1.f, 1);
    }

    // ---- 5) flash attention
    flash_hmma<<<dim3(T_/128, B_*H_), 256, FSM>>>(qh, kh, vh, atth);

    // ---- 6) out projection
    {
        GemmArgs oa = {atth, woh, bo, out, nullptr};
        hmma_ps<<<dim3(4, 128, 1), 256, GSM>>>(oa, oa, E_, E_, 1.f, 0);
    }

    (void)in_sizes; (void)n_in; (void)out_size;
}